// round 8
// baseline (speedup 1.0000x reference)
#include <cuda_runtime.h>

// Problem constants (fixed shapes)
#define BATCH 4
#define CH    256
#define HH    64
#define WW    64
#define HWSZ  4096          // HH*WW
#define KKN   9             // 3x3
#define DGN   4             // deform groups
#define CGN   64            // channels per deform group
#define KDIM  2304          // KKN*CH  (GEMM K)
#define NDIM  16384         // BATCH*HWSZ (GEMM N)
#define GROUPS 32
#define GRP_ELEMS 32768     // (CH/GROUPS)*HWSZ = 8*4096

// Scratch (device globals — allocation-free per harness rules)
__device__ float g_col[(size_t)KDIM * NDIM];   // [k][n], k = kk*256 + c, n = b*4096 + hw  (151 MB)
__device__ float g_wt[KDIM * CH];              // [k][o]  (2.4 MB)
__device__ float g_sum[BATCH * GROUPS];
__device__ float g_sqs[BATCH * GROUPS];

// ---------------------------------------------------------------------------
// 1) Repack weight: w_deform[o][c][ky][kx] -> g_wt[(kk*256+c)*256 + o]
// ---------------------------------------------------------------------------
__global__ void repack_kernel(const float* __restrict__ wd) {
    int d = blockIdx.x * 256 + threadIdx.x;      // < 589824
    int o  = d & 255;
    int k  = d >> 8;
    int c  = k & 255;
    int kk = k >> 8;
    g_wt[d] = wd[(o * CH + c) * KKN + kk];
}

// ---------------------------------------------------------------------------
// 2) Fused offset-projection + deformable im2col.
//    One thread per (b, dg, kk, hw). Writes 64 channels of col.
// ---------------------------------------------------------------------------
__global__ void im2col_kernel(const float* __restrict__ x,
                              const float* __restrict__ shp,
                              const float* __restrict__ w_off) {
    int hw = blockIdx.x * 256 + threadIdx.x;     // 0..4095
    int z  = blockIdx.y;                         // b*36 + dg*9 + kk
    int kk = z % KKN;
    int dg = (z / KKN) % DGN;
    int b  = z / (KKN * DGN);
    int h  = hw >> 6;
    int w  = hw & 63;

    // shape[b, i, h, w], i in 0..3
    float s0 = shp[((b * 4 + 0) << 12) + hw];
    float s1 = shp[((b * 4 + 1) << 12) + hw];
    float s2 = shp[((b * 4 + 2) << 12) + hw];
    float s3 = shp[((b * 4 + 3) << 12) + hw];

    // offset channel = dg*18 + kk*2 + {0:dy, 1:dx}, each a row of 4 in w_off
    const float* wo = w_off + (dg * 18 + kk * 2) * 4;
    float dy = wo[0] * s0 + wo[1] * s1 + wo[2] * s2 + wo[3] * s3;
    float dx = wo[4] * s0 + wo[5] * s1 + wo[6] * s2 + wo[7] * s3;

    int ky = kk / 3, kx = kk % 3;
    float yf = (float)(h - 1 + ky) + dy;
    float xf = (float)(w - 1 + kx) + dx;
    float y0f = floorf(yf), x0f = floorf(xf);
    float wy1 = yf - y0f,  wx1 = xf - x0f;
    float wy0 = 1.0f - wy1, wx0 = 1.0f - wx1;
    int y0 = (int)y0f, x0 = (int)x0f;
    int y1 = y0 + 1,   x1 = x0 + 1;

    bool vy0 = (y0 >= 0) & (y0 < HH);
    bool vy1 = (y1 >= 0) & (y1 < HH);
    bool vx0 = (x0 >= 0) & (x0 < WW);
    bool vx1 = (x1 >= 0) & (x1 < WW);
    int y0c = min(max(y0, 0), HH - 1), y1c = min(max(y1, 0), HH - 1);
    int x0c = min(max(x0, 0), WW - 1), x1c = min(max(x1, 0), WW - 1);

    float w00 = wy0 * wx0 * (float)(vy0 & vx0);
    float w01 = wy0 * wx1 * (float)(vy0 & vx1);
    float w10 = wy1 * wx0 * (float)(vy1 & vx0);
    float w11 = wy1 * wx1 * (float)(vy1 & vx1);

    int i00 = y0c * WW + x0c;
    int i01 = y0c * WW + x1c;
    int i10 = y1c * WW + x0c;
    int i11 = y1c * WW + x1c;

    const float* xb = x + ((size_t)(b * CH + dg * CGN) << 12);
    float* colp = g_col + (size_t)(kk * 256 + dg * CGN) * NDIM + (b << 12) + hw;

    #pragma unroll 4
    for (int cg = 0; cg < CGN; cg++) {
        const float* xc = xb + ((size_t)cg << 12);
        float v = w00 * xc[i00] + w01 * xc[i01] + w10 * xc[i10] + w11 * xc[i11];
        colp[(size_t)cg * NDIM] = v;
    }
}

// ---------------------------------------------------------------------------
// 3) SGEMM: out[o][n] = sum_k g_wt[k][o] * g_col[k][n]
//    BM=BN=128, BK=8, 256 threads, 8x8 per thread. grid = (128 nTiles, 2 oTiles)
// ---------------------------------------------------------------------------
__global__ __launch_bounds__(256, 2)
void gemm_kernel(float* __restrict__ out) {
    __shared__ float As[8][128];   // [kb][o]
    __shared__ float Bs[8][128];   // [kb][n]

    const int tid = threadIdx.x;
    const int nBase = blockIdx.x * 128;
    const int oBase = blockIdx.y * 128;
    const int tr = tid >> 4;            // 0..15 -> o sub-tile
    const int tc = tid & 15;            // 0..15 -> n sub-tile
    const int lr = tid >> 5;            // 0..7  load row (k)
    const int lc = (tid & 31) * 4;      // 0..124 load col

    float acc[8][8];
    #pragma unroll
    for (int i = 0; i < 8; i++)
        #pragma unroll
        for (int j = 0; j < 8; j++) acc[i][j] = 0.0f;

    for (int k0 = 0; k0 < KDIM; k0 += 8) {
        float4 av = *(const float4*)(g_wt + (size_t)(k0 + lr) * CH + oBase + lc);
        float4 bv = *(const float4*)(g_col + (size_t)(k0 + lr) * NDIM + nBase + lc);
        *(float4*)&As[lr][lc] = av;
        *(float4*)&Bs[lr][lc] = bv;
        __syncthreads();

        #pragma unroll
        for (int kb = 0; kb < 8; kb++) {
            float4 a0 = *(const float4*)&As[kb][tr * 8];
            float4 a1 = *(const float4*)&As[kb][tr * 8 + 4];
            float4 b0 = *(const float4*)&Bs[kb][tc * 8];
            float4 b1 = *(const float4*)&Bs[kb][tc * 8 + 4];
            float aR[8] = {a0.x, a0.y, a0.z, a0.w, a1.x, a1.y, a1.z, a1.w};
            float bR[8] = {b0.x, b0.y, b0.z, b0.w, b1.x, b1.y, b1.z, b1.w};
            #pragma unroll
            for (int i = 0; i < 8; i++)
                #pragma unroll
                for (int j = 0; j < 8; j++)
                    acc[i][j] += aR[i] * bR[j];
        }
        __syncthreads();
    }

    // n = b*4096 + hw; whole block shares b since 128 | 4096
    const int b = nBase >> 12;
    const int hwBase = (nBase & 4095) + tc * 8;
    #pragma unroll
    for (int i = 0; i < 8; i++) {
        int o = oBase + tr * 8 + i;
        float* op = out + ((size_t)(b * CH + o) << 12) + hwBase;
        *(float4*)op       = make_float4(acc[i][0], acc[i][1], acc[i][2], acc[i][3]);
        *(float4*)(op + 4) = make_float4(acc[i][4], acc[i][5], acc[i][6], acc[i][7]);
    }
}

// ---------------------------------------------------------------------------
// 4) GroupNorm stats: one block per (b, group); group data is contiguous.
// ---------------------------------------------------------------------------
__global__ void stats_kernel(const float* __restrict__ out) {
    int grp = blockIdx.x;   // b*32 + g
    const float* p = out + (size_t)grp * GRP_ELEMS;
    float s = 0.0f, q = 0.0f;
    for (int i = threadIdx.x; i < GRP_ELEMS; i += 256) {
        float v = p[i];
        s += v;
        q += v * v;
    }
    __shared__ float ss[256], qq[256];
    ss[threadIdx.x] = s; qq[threadIdx.x] = q;
    __syncthreads();
    for (int st = 128; st > 0; st >>= 1) {
        if (threadIdx.x < st) {
            ss[threadIdx.x] += ss[threadIdx.x + st];
            qq[threadIdx.x] += qq[threadIdx.x + st];
        }
        __syncthreads();
    }
    if (threadIdx.x == 0) {
        g_sum[grp] = ss[0];
        g_sqs[grp] = qq[0];
    }
}

// ---------------------------------------------------------------------------
// 5) Normalize + affine + ReLU, in place, float4-vectorized.
// ---------------------------------------------------------------------------
__global__ void norm_relu_kernel(float* __restrict__ out,
                                 const float* __restrict__ gamma,
                                 const float* __restrict__ beta) {
    int t  = blockIdx.x * 256 + threadIdx.x;   // < 1048576
    int i4 = t * 4;
    int b  = i4 >> 20;                         // /(256*4096)
    int c  = (i4 >> 12) & 255;
    int grp = b * GROUPS + (c >> 3);
    float m   = g_sum[grp] * (1.0f / GRP_ELEMS);
    float var = g_sqs[grp] * (1.0f / GRP_ELEMS) - m * m;
    float inv = rsqrtf(var + 1e-5f);
    float ga  = gamma[c] * inv;
    float be  = beta[c] - m * ga;
    float4 v = *(float4*)(out + i4);
    v.x = fmaxf(v.x * ga + be, 0.0f);
    v.y = fmaxf(v.y * ga + be, 0.0f);
    v.z = fmaxf(v.z * ga + be, 0.0f);
    v.w = fmaxf(v.w * ga + be, 0.0f);
    *(float4*)(out + i4) = v;
}

// ---------------------------------------------------------------------------
extern "C" void kernel_launch(void* const* d_in, const int* in_sizes, int n_in,
                              void* d_out, int out_size) {
    const float* x      = (const float*)d_in[0];   // (4,256,64,64)
    const float* shp    = (const float*)d_in[1];   // (4,4,64,64)
    const float* w_off  = (const float*)d_in[2];   // (72,4)
    const float* w_def  = (const float*)d_in[3];   // (256,256,3,3)
    const float* gamma  = (const float*)d_in[4];   // (256,)
    const float* beta   = (const float*)d_in[5];   // (256,)
    float* out = (float*)d_out;                    // (4,256,64,64) fp32

    repack_kernel<<<2304, 256>>>(w_def);
    im2col_kernel<<<dim3(16, BATCH * DGN * KKN), 256>>>(x, shp, w_off);
    gemm_kernel<<<dim3(128, 2), 256>>>(out);
    stats_kernel<<<BATCH * GROUPS, 256>>>(out);
    norm_relu_kernel<<<4096, 256>>>(out, gamma, beta);
}

// round 10
// speedup vs baseline: 2.3162x; 2.3162x over previous
#include <cuda_runtime.h>
#include <cuda_bf16.h>
#include <cstdint>

// Problem constants (fixed shapes)
#define BATCH 4
#define CH    256
#define HH    64
#define WW    64
#define HWSZ  4096
#define KKN   9
#define DGN   4
#define CGN   64
#define KDIM  2304          // KKN*CH (GEMM K), k = c*9 + kk
#define NDIM  16384         // BATCH*HWSZ (GEMM N)
#define GROUPS 32
#define GRP_ELEMS 32768

// ---- scratch (device globals; allocation-free) ----
__device__ __align__(16) __nv_bfloat16 g_col_hi[(size_t)KDIM * NDIM];  // [k][n]
__device__ __align__(16) __nv_bfloat16 g_col_lo[(size_t)KDIM * NDIM];
__device__ __align__(16) __nv_bfloat16 g_wt_hi[CH * KDIM];             // [o][k]
__device__ __align__(16) __nv_bfloat16 g_wt_lo[CH * KDIM];
__device__ float g_sum[BATCH * GROUPS];
__device__ float g_sqs[BATCH * GROUPS];

// ---------------------------------------------------------------------------
// PTX helpers — family-agnostic only (compute_103 target: no tcgen05/TMA)
// ---------------------------------------------------------------------------
__device__ __forceinline__ uint32_t smem_u32(const void* p) {
    uint32_t a;
    asm("{ .reg .u64 t; cvta.to.shared.u64 t, %1; cvt.u32.u64 %0, t; }" : "=r"(a) : "l"(p));
    return a;
}
__device__ __forceinline__ void cp16(uint32_t dst, const void* src) {
    asm volatile("cp.async.cg.shared.global [%0], [%1], 16;" :: "r"(dst), "l"(src) : "memory");
}
#define CP_COMMIT() asm volatile("cp.async.commit_group;" ::: "memory")
#define CP_WAIT2()  asm volatile("cp.async.wait_group 2;" ::: "memory")

#define LDSM_X4(r, addr) \
    asm volatile("ldmatrix.sync.aligned.m8n8.x4.shared.b16 {%0,%1,%2,%3}, [%4];" \
        : "=r"((r)[0]), "=r"((r)[1]), "=r"((r)[2]), "=r"((r)[3]) : "r"(addr))
#define LDSM_X4T(r0, r1, r2, r3, addr) \
    asm volatile("ldmatrix.sync.aligned.m8n8.x4.trans.shared.b16 {%0,%1,%2,%3}, [%4];" \
        : "=r"(r0), "=r"(r1), "=r"(r2), "=r"(r3) : "r"(addr))

#define MMA(d, a, b) \
    asm volatile("mma.sync.aligned.m16n8k16.row.col.f32.bf16.bf16.f32 " \
        "{%0,%1,%2,%3}, {%4,%5,%6,%7}, {%8,%9}, {%0,%1,%2,%3};" \
        : "+f"((d)[0]), "+f"((d)[1]), "+f"((d)[2]), "+f"((d)[3]) \
        : "r"((a)[0]), "r"((a)[1]), "r"((a)[2]), "r"((a)[3]), "r"((b)[0]), "r"((b)[1]))

__device__ __forceinline__ void split_bf16(float v, __nv_bfloat16& hi, __nv_bfloat16& lo) {
    hi = __float2bfloat16(v);
    lo = __float2bfloat16(v - __bfloat162float(hi));
}

// ---------------------------------------------------------------------------
// 1) Weight split: w_deform natural layout [o][c][kk] == [o][k], k=c*9+kk
// ---------------------------------------------------------------------------
__global__ void repack_kernel(const float* __restrict__ wd) {
    int d = blockIdx.x * 256 + threadIdx.x;   // < 589824
    __nv_bfloat16 hi, lo;
    split_bf16(wd[d], hi, lo);
    g_wt_hi[d] = hi;
    g_wt_lo[d] = lo;
}

// ---------------------------------------------------------------------------
// 2) Fused offset-projection + deformable im2col -> col hi/lo [k][n]
// ---------------------------------------------------------------------------
__global__ void im2col_kernel(const float* __restrict__ x,
                              const float* __restrict__ shp,
                              const float* __restrict__ w_off) {
    int hw = blockIdx.x * 256 + threadIdx.x;
    int z  = blockIdx.y;                      // b*36 + dg*9 + kk
    int kk = z % KKN;
    int dg = (z / KKN) % DGN;
    int b  = z / (KKN * DGN);
    int h  = hw >> 6;
    int w  = hw & 63;

    float s0 = shp[((b * 4 + 0) << 12) + hw];
    float s1 = shp[((b * 4 + 1) << 12) + hw];
    float s2 = shp[((b * 4 + 2) << 12) + hw];
    float s3 = shp[((b * 4 + 3) << 12) + hw];

    const float* wo = w_off + (dg * 18 + kk * 2) * 4;
    float dy = wo[0] * s0 + wo[1] * s1 + wo[2] * s2 + wo[3] * s3;
    float dx = wo[4] * s0 + wo[5] * s1 + wo[6] * s2 + wo[7] * s3;

    int ky = kk / 3, kx = kk % 3;
    float yf = (float)(h - 1 + ky) + dy;
    float xf = (float)(w - 1 + kx) + dx;
    float y0f = floorf(yf), x0f = floorf(xf);
    float wy1 = yf - y0f,  wx1 = xf - x0f;
    float wy0 = 1.0f - wy1, wx0 = 1.0f - wx1;
    int y0 = (int)y0f, x0 = (int)x0f;
    int y1 = y0 + 1,   x1 = x0 + 1;

    bool vy0 = (y0 >= 0) & (y0 < HH);
    bool vy1 = (y1 >= 0) & (y1 < HH);
    bool vx0 = (x0 >= 0) & (x0 < WW);
    bool vx1 = (x1 >= 0) & (x1 < WW);
    int y0c = min(max(y0, 0), HH - 1), y1c = min(max(y1, 0), HH - 1);
    int x0c = min(max(x0, 0), WW - 1), x1c = min(max(x1, 0), WW - 1);

    float w00 = wy0 * wx0 * (float)(vy0 & vx0);
    float w01 = wy0 * wx1 * (float)(vy0 & vx1);
    float w10 = wy1 * wx0 * (float)(vy1 & vx0);
    float w11 = wy1 * wx1 * (float)(vy1 & vx1);

    int i00 = y0c * WW + x0c;
    int i01 = y0c * WW + x1c;
    int i10 = y1c * WW + x0c;
    int i11 = y1c * WW + x1c;

    const float* xb = x + ((size_t)(b * CH + dg * CGN) << 12);
    size_t nIdx = ((size_t)b << 12) + hw;

    #pragma unroll 4
    for (int cg = 0; cg < CGN; cg++) {
        const float* xc = xb + ((size_t)cg << 12);
        float v = w00 * xc[i00] + w01 * xc[i01] + w10 * xc[i10] + w11 * xc[i11];
        int k = (dg * CGN + cg) * KKN + kk;
        __nv_bfloat16 hi, lo;
        split_bf16(v, hi, lo);
        g_col_hi[(size_t)k * NDIM + nIdx] = hi;
        g_col_lo[(size_t)k * NDIM + nIdx] = lo;
    }
}

// ---------------------------------------------------------------------------
// 3) Split-bf16 HMMA GEMM: out[o][n] = sum_k wt[o][k] * col[k][n]
//    CTA 128(o) x 128(n), K-chunk 32, 3-stage cp.async pipeline, 8 warps (4x2).
//    3 products per chunk: hi*hi + hi*lo + lo*hi (f32 accumulate).
// ---------------------------------------------------------------------------
#define KB       32
#define NCHUNK   72                 // 2304/32
#define A_STRIDE 80                 // 64B data + pad -> conflict-free ldmatrix
#define ST_AHI   0
#define ST_ALO   10240
#define ST_BHI   20480              // B rows: 256B, XOR-swizzled 16B granules
#define ST_BLO   28672
#define STAGE    36864
#define NSTAGES  3
#define GEMM_SMEM (NSTAGES * STAGE) // 110592

// Issue one stage of cp.async loads (both A planes + both B planes)
#define ISSUE(ch)                                                            \
    do {                                                                     \
        if ((ch) < NCHUNK) {                                                 \
            const int k0_ = (ch) * KB;                                       \
            const uint32_t base_ = sb + ((ch) % NSTAGES) * STAGE;            \
            int g_ = tid;                                                    \
            for (int p_ = 0; p_ < 2; p_++, g_ += 256) {                      \
                int m_ = g_ >> 2, kg_ = g_ & 3;                              \
                size_t ga_ = (size_t)(oBase + m_) * KDIM + k0_ + kg_ * 8;    \
                uint32_t da_ = base_ + m_ * A_STRIDE + kg_ * 16;             \
                cp16(da_ + ST_AHI, g_wt_hi + ga_);                           \
                cp16(da_ + ST_ALO, g_wt_lo + ga_);                           \
                int k_ = g_ >> 4, ng_ = g_ & 15;                             \
                size_t gb_ = (size_t)(k0_ + k_) * NDIM + nBase + ng_ * 8;    \
                uint32_t db_ = base_ + k_ * 256 + ((ng_ ^ (k_ & 7)) << 4);   \
                cp16(db_ + ST_BHI, g_col_hi + gb_);                          \
                cp16(db_ + ST_BLO, g_col_lo + gb_);                          \
            }                                                                \
        }                                                                    \
        CP_COMMIT();                                                         \
    } while (0)

__global__ __launch_bounds__(256, 1)
void gemm_mma_kernel(float* __restrict__ out) {
    extern __shared__ __align__(128) char smem[];
    const uint32_t sb = smem_u32(smem);
    const int tid  = threadIdx.x;
    const int lane = tid & 31;
    const int wid  = tid >> 5;
    const int warpM = wid & 3;      // 0..3 -> m offset warpM*32
    const int warpN = wid >> 1 >> 1;// 0..1 -> n offset warpN*64
    const int nBase = blockIdx.x * 128;
    const int oBase = blockIdx.y * 128;

    float acc[2][8][4];
    #pragma unroll
    for (int mt = 0; mt < 2; mt++)
        #pragma unroll
        for (int nt = 0; nt < 8; nt++)
            #pragma unroll
            for (int q = 0; q < 4; q++) acc[mt][nt][q] = 0.0f;

    // ldmatrix lane geometry (computed once)
    const int arow = (lane & 7) + ((lane >> 3) & 1) * 8;   // A: row within 16
    const int asel = lane >> 4;                            // A: k8 group select
    const int bk   = lane & 15;                            // B: k row within 16
    const int bsel = lane >> 4;                            // B: n8 group select

    ISSUE(0); ISSUE(1); ISSUE(2);

    for (int ch = 0; ch < NCHUNK; ch++) {
        CP_WAIT2();
        __syncthreads();
        const uint32_t buf = sb + (ch % NSTAGES) * STAGE;

        #pragma unroll
        for (int kq = 0; kq < 2; kq++) {
            uint32_t aHi[2][4], aLo[2][4], bHi[8][2], bLo[8][2];

            #pragma unroll
            for (int mt = 0; mt < 2; mt++) {
                uint32_t ad = buf + (warpM * 32 + mt * 16 + arow) * A_STRIDE
                                  + (kq * 2 + asel) * 16;
                LDSM_X4(aHi[mt], ad + ST_AHI);
                LDSM_X4(aLo[mt], ad + ST_ALO);
            }
            {
                int kr = kq * 16 + bk;
                #pragma unroll
                for (int i = 0; i < 4; i++) {
                    int ng = warpN * 8 + 2 * i + bsel;
                    uint32_t bd = buf + kr * 256 + ((ng ^ (kr & 7)) << 4);
                    LDSM_X4T(bHi[2*i][0], bHi[2*i][1], bHi[2*i+1][0], bHi[2*i+1][1],
                             bd + ST_BHI);
                    LDSM_X4T(bLo[2*i][0], bLo[2*i][1], bLo[2*i+1][0], bLo[2*i+1][1],
                             bd + ST_BLO);
                }
            }
            // hi*hi
            #pragma unroll
            for (int mt = 0; mt < 2; mt++)
                #pragma unroll
                for (int nt = 0; nt < 8; nt++) MMA(acc[mt][nt], aHi[mt], bHi[nt]);
            // hi*lo
            #pragma unroll
            for (int mt = 0; mt < 2; mt++)
                #pragma unroll
                for (int nt = 0; nt < 8; nt++) MMA(acc[mt][nt], aHi[mt], bLo[nt]);
            // lo*hi
            #pragma unroll
            for (int mt = 0; mt < 2; mt++)
                #pragma unroll
                for (int nt = 0; nt < 8; nt++) MMA(acc[mt][nt], aLo[mt], bHi[nt]);
        }
        __syncthreads();
        ISSUE(ch + 3);
    }

    // Epilogue: direct f32x2 stores (32B sectors per 4 lanes, fully dense)
    const int b   = nBase >> 12;
    const int hwB = (nBase & 4095) + warpN * 64;
    #pragma unroll
    for (int mt = 0; mt < 2; mt++) {
        int o = oBase + warpM * 32 + mt * 16 + (lane >> 2);
        float* r0 = out + ((size_t)(b * CH + o) << 12) + hwB;
        float* r1 = r0 + ((size_t)8 << 12);   // row o+8
        #pragma unroll
        for (int nt = 0; nt < 8; nt++) {
            int c = nt * 8 + (lane & 3) * 2;
            *(float2*)(r0 + c) = make_float2(acc[mt][nt][0], acc[mt][nt][1]);
            *(float2*)(r1 + c) = make_float2(acc[mt][nt][2], acc[mt][nt][3]);
        }
    }
}

// ---------------------------------------------------------------------------
// 4) GroupNorm stats
// ---------------------------------------------------------------------------
__global__ void stats_kernel(const float* __restrict__ out) {
    int grp = blockIdx.x;
    const float* p = out + (size_t)grp * GRP_ELEMS;
    float s = 0.0f, q = 0.0f;
    for (int i = threadIdx.x; i < GRP_ELEMS; i += 256) {
        float v = p[i];
        s += v;
        q += v * v;
    }
    __shared__ float ss[256], qq[256];
    ss[threadIdx.x] = s; qq[threadIdx.x] = q;
    __syncthreads();
    for (int st = 128; st > 0; st >>= 1) {
        if (threadIdx.x < st) {
            ss[threadIdx.x] += ss[threadIdx.x + st];
            qq[threadIdx.x] += qq[threadIdx.x + st];
        }
        __syncthreads();
    }
    if (threadIdx.x == 0) {
        g_sum[grp] = ss[0];
        g_sqs[grp] = qq[0];
    }
}

// ---------------------------------------------------------------------------
// 5) Normalize + affine + ReLU
// ---------------------------------------------------------------------------
__global__ void norm_relu_kernel(float* __restrict__ out,
                                 const float* __restrict__ gamma,
                                 const float* __restrict__ beta) {
    int t  = blockIdx.x * 256 + threadIdx.x;
    int i4 = t * 4;
    int b  = i4 >> 20;
    int c  = (i4 >> 12) & 255;
    int grp = b * GROUPS + (c >> 3);
    float m   = g_sum[grp] * (1.0f / GRP_ELEMS);
    float var = g_sqs[grp] * (1.0f / GRP_ELEMS) - m * m;
    float inv = rsqrtf(var + 1e-5f);
    float ga  = gamma[c] * inv;
    float be  = beta[c] - m * ga;
    float4 v = *(float4*)(out + i4);
    v.x = fmaxf(v.x * ga + be, 0.0f);
    v.y = fmaxf(v.y * ga + be, 0.0f);
    v.z = fmaxf(v.z * ga + be, 0.0f);
    v.w = fmaxf(v.w * ga + be, 0.0f);
    *(float4*)(out + i4) = v;
}

// ---------------------------------------------------------------------------
extern "C" void kernel_launch(void* const* d_in, const int* in_sizes, int n_in,
                              void* d_out, int out_size) {
    const float* x      = (const float*)d_in[0];
    const float* shp    = (const float*)d_in[1];
    const float* w_off  = (const float*)d_in[2];
    const float* w_def  = (const float*)d_in[3];
    const float* gamma  = (const float*)d_in[4];
    const float* beta   = (const float*)d_in[5];
    float* out = (float*)d_out;

    cudaFuncSetAttribute(gemm_mma_kernel,
                         cudaFuncAttributeMaxDynamicSharedMemorySize, GEMM_SMEM);

    repack_kernel<<<2304, 256>>>(w_def);
    im2col_kernel<<<dim3(16, BATCH * DGN * KKN), 256>>>(x, shp, w_off);
    gemm_mma_kernel<<<dim3(128, 2), 256, GEMM_SMEM>>>(out);
    stats_kernel<<<BATCH * GROUPS, 256>>>(out);
    norm_relu_kernel<<<4096, 256>>>(out, gamma, beta);
}

// round 11
// speedup vs baseline: 3.4698x; 1.4981x over previous
#include <cuda_runtime.h>
#include <cuda_fp16.h>
#include <cstdint>

// Problem constants (fixed shapes)
#define BATCH 4
#define CH    256
#define HH    64
#define WW    64
#define HWSZ  4096
#define KKN   9
#define DGN   4
#define CGN   64
#define KDIM  2304          // KKN*CH (GEMM K), k = c*9 + kk
#define NDIM  16384         // BATCH*HWSZ (GEMM N)
#define GROUPS 32
#define GRP_ELEMS 32768

// ---- scratch (device globals; allocation-free) ----
__device__ __align__(16) __half g_col[(size_t)KDIM * NDIM];   // [k][n], single fp16 plane (75 MB)
__device__ __align__(16) __half g_wt_hi[CH * KDIM];           // [o][k]
__device__ __align__(16) __half g_wt_lo[CH * KDIM];
__device__ float g_sum[BATCH * GROUPS];
__device__ float g_sqs[BATCH * GROUPS];

// ---------------------------------------------------------------------------
// PTX helpers — family-agnostic only (compute_103 target: no tcgen05/TMA)
// ---------------------------------------------------------------------------
__device__ __forceinline__ uint32_t smem_u32(const void* p) {
    uint32_t a;
    asm("{ .reg .u64 t; cvta.to.shared.u64 t, %1; cvt.u32.u64 %0, t; }" : "=r"(a) : "l"(p));
    return a;
}
__device__ __forceinline__ void cp16(uint32_t dst, const void* src) {
    asm volatile("cp.async.cg.shared.global [%0], [%1], 16;" :: "r"(dst), "l"(src) : "memory");
}
#define CP_COMMIT() asm volatile("cp.async.commit_group;" ::: "memory")
#define CP_WAIT1()  asm volatile("cp.async.wait_group 1;" ::: "memory")

#define LDSM_X4(r, addr) \
    asm volatile("ldmatrix.sync.aligned.m8n8.x4.shared.b16 {%0,%1,%2,%3}, [%4];" \
        : "=r"((r)[0]), "=r"((r)[1]), "=r"((r)[2]), "=r"((r)[3]) : "r"(addr))
#define LDSM_X4T(r0, r1, r2, r3, addr) \
    asm volatile("ldmatrix.sync.aligned.m8n8.x4.trans.shared.b16 {%0,%1,%2,%3}, [%4];" \
        : "=r"(r0), "=r"(r1), "=r"(r2), "=r"(r3) : "r"(addr))

#define MMA(d, a, b) \
    asm volatile("mma.sync.aligned.m16n8k16.row.col.f32.f16.f16.f32 " \
        "{%0,%1,%2,%3}, {%4,%5,%6,%7}, {%8,%9}, {%0,%1,%2,%3};" \
        : "+f"((d)[0]), "+f"((d)[1]), "+f"((d)[2]), "+f"((d)[3]) \
        : "r"((a)[0]), "r"((a)[1]), "r"((a)[2]), "r"((a)[3]), "r"((b)[0]), "r"((b)[1]))

// ---------------------------------------------------------------------------
// 1) Weight split (fp16 hi/lo) + zero GN stat accumulators
// ---------------------------------------------------------------------------
__global__ void repack_kernel(const float* __restrict__ wd) {
    int d = blockIdx.x * 256 + threadIdx.x;   // < 589824
    float v = wd[d];
    __half hi = __float2half_rn(v);
    __half lo = __float2half_rn(v - __half2float(hi));
    g_wt_hi[d] = hi;
    g_wt_lo[d] = lo;
    if (blockIdx.x == 0 && threadIdx.x < BATCH * GROUPS) {
        g_sum[threadIdx.x] = 0.0f;
        g_sqs[threadIdx.x] = 0.0f;
    }
}

// ---------------------------------------------------------------------------
// 2) Fused offset-projection + deformable im2col -> fp16 col [k][n]
//    Each thread handles 2 consecutive hw -> packed u32 stores.
// ---------------------------------------------------------------------------
__global__ void im2col_kernel(const float* __restrict__ x,
                              const float* __restrict__ shp,
                              const float* __restrict__ w_off) {
    int tid = threadIdx.x;
    int z  = blockIdx.y;                      // b*36 + dg*9 + kk
    int kk = z % KKN;
    int dg = (z / KKN) % DGN;
    int b  = z / (KKN * DGN);

    float w4[2][4];
    int   id[2][4];

    #pragma unroll
    for (int u = 0; u < 2; u++) {
        int hw = blockIdx.x * 512 + tid * 2 + u;
        int h  = hw >> 6;
        int w  = hw & 63;

        float s0 = shp[((b * 4 + 0) << 12) + hw];
        float s1 = shp[((b * 4 + 1) << 12) + hw];
        float s2 = shp[((b * 4 + 2) << 12) + hw];
        float s3 = shp[((b * 4 + 3) << 12) + hw];

        const float* wo = w_off + (dg * 18 + kk * 2) * 4;
        float dy = wo[0] * s0 + wo[1] * s1 + wo[2] * s2 + wo[3] * s3;
        float dx = wo[4] * s0 + wo[5] * s1 + wo[6] * s2 + wo[7] * s3;

        int ky = kk / 3, kx = kk % 3;
        float yf = (float)(h - 1 + ky) + dy;
        float xf = (float)(w - 1 + kx) + dx;
        float y0f = floorf(yf), x0f = floorf(xf);
        float wy1 = yf - y0f,  wx1 = xf - x0f;
        float wy0 = 1.0f - wy1, wx0 = 1.0f - wx1;
        int y0 = (int)y0f, x0 = (int)x0f;
        int y1 = y0 + 1,   x1 = x0 + 1;

        bool vy0 = (y0 >= 0) & (y0 < HH);
        bool vy1 = (y1 >= 0) & (y1 < HH);
        bool vx0 = (x0 >= 0) & (x0 < WW);
        bool vx1 = (x1 >= 0) & (x1 < WW);
        int y0c = min(max(y0, 0), HH - 1), y1c = min(max(y1, 0), HH - 1);
        int x0c = min(max(x0, 0), WW - 1), x1c = min(max(x1, 0), WW - 1);

        w4[u][0] = wy0 * wx0 * (float)(vy0 & vx0);
        w4[u][1] = wy0 * wx1 * (float)(vy0 & vx1);
        w4[u][2] = wy1 * wx0 * (float)(vy1 & vx0);
        w4[u][3] = wy1 * wx1 * (float)(vy1 & vx1);
        id[u][0] = y0c * WW + x0c;
        id[u][1] = y0c * WW + x1c;
        id[u][2] = y1c * WW + x0c;
        id[u][3] = y1c * WW + x1c;
    }

    const float* xb = x + ((size_t)(b * CH + dg * CGN) << 12);
    size_t nIdx = ((size_t)b << 12) + blockIdx.x * 512 + tid * 2;

    #pragma unroll 4
    for (int cg = 0; cg < CGN; cg++) {
        const float* xc = xb + ((size_t)cg << 12);
        float v0 = w4[0][0] * xc[id[0][0]] + w4[0][1] * xc[id[0][1]]
                 + w4[0][2] * xc[id[0][2]] + w4[0][3] * xc[id[0][3]];
        float v1 = w4[1][0] * xc[id[1][0]] + w4[1][1] * xc[id[1][1]]
                 + w4[1][2] * xc[id[1][2]] + w4[1][3] * xc[id[1][3]];
        int k = (dg * CGN + cg) * KKN + kk;
        __half2 hv = __floats2half2_rn(v0, v1);
        *(uint32_t*)(g_col + (size_t)k * NDIM + nIdx) = *(uint32_t*)&hv;
    }
}

// ---------------------------------------------------------------------------
// 3) Split-fp16 HMMA GEMM (2 products): out = (wt_hi + wt_lo) * col
//    CTA 128(o) x 128(n), K-chunk 64, 2-stage cp.async, 8 warps (4x2),
//    fused GroupNorm partial-stats in epilogue.
// ---------------------------------------------------------------------------
#define KB       64
#define NCHUNK   36                 // 2304/64
#define A_STRIDE 144                // 128B data + 16B pad (conflict-free ldmatrix)
#define ST_AHI   0
#define ST_ALO   18432
#define ST_B     36864              // B rows: 256B, XOR-swizzled 16B granules
#define STAGE    53248
#define GEMM_SMEM (2 * STAGE)       // 106496 -> 2 CTAs/SM

#define ISSUE(ch)                                                            \
    do {                                                                     \
        if ((ch) < NCHUNK) {                                                 \
            const int k0_ = (ch) * KB;                                       \
            const uint32_t base_ = sb + ((ch) & 1) * STAGE;                  \
            _Pragma("unroll")                                                \
            for (int p_ = 0; p_ < 4; p_++) {                                 \
                int a_ = tid + p_ * 256;                                     \
                int m_ = a_ >> 3, kg_ = a_ & 7;                              \
                size_t ga_ = (size_t)(oBase + m_) * KDIM + k0_ + kg_ * 8;    \
                uint32_t da_ = base_ + m_ * A_STRIDE + kg_ * 16;             \
                cp16(da_ + ST_AHI, g_wt_hi + ga_);                           \
                cp16(da_ + ST_ALO, g_wt_lo + ga_);                           \
                int k_ = a_ >> 4, ng_ = a_ & 15;                             \
                size_t gb_ = (size_t)(k0_ + k_) * NDIM + nBase + ng_ * 8;    \
                uint32_t db_ = base_ + ST_B + k_ * 256 + ((ng_ ^ (k_ & 7)) << 4); \
                cp16(db_, g_col + gb_);                                      \
            }                                                                \
        }                                                                    \
        CP_COMMIT();                                                         \
    } while (0)

__global__ __launch_bounds__(256, 2)
void gemm_mma_kernel(float* __restrict__ out) {
    extern __shared__ __align__(128) char smem[];
    const uint32_t sb = smem_u32(smem);
    const int tid  = threadIdx.x;
    const int lane = tid & 31;
    const int wid  = tid >> 5;
    const int warpM = wid & 3;      // m offset warpM*32
    const int warpN = wid >> 2;     // n offset warpN*64
    const int nBase = blockIdx.x * 128;
    const int oBase = blockIdx.y * 128;

    float acc[2][8][4];
    #pragma unroll
    for (int mt = 0; mt < 2; mt++)
        #pragma unroll
        for (int nt = 0; nt < 8; nt++)
            #pragma unroll
            for (int q = 0; q < 4; q++) acc[mt][nt][q] = 0.0f;

    const int arow = (lane & 7) + ((lane >> 3) & 1) * 8;
    const int asel = lane >> 4;
    const int bk   = lane & 15;
    const int bsel = lane >> 4;

    ISSUE(0); ISSUE(1);

    for (int ch = 0; ch < NCHUNK; ch++) {
        CP_WAIT1();
        __syncthreads();
        const uint32_t buf = sb + (ch & 1) * STAGE;

        #pragma unroll
        for (int kq = 0; kq < 4; kq++) {
            uint32_t aHi[2][4], aLo[2][4], bF[8][2];

            #pragma unroll
            for (int mt = 0; mt < 2; mt++) {
                uint32_t ad = buf + (warpM * 32 + mt * 16 + arow) * A_STRIDE
                                  + (kq * 2 + asel) * 16;
                LDSM_X4(aHi[mt], ad + ST_AHI);
                LDSM_X4(aLo[mt], ad + ST_ALO);
            }
            {
                int kr = kq * 16 + bk;
                #pragma unroll
                for (int i = 0; i < 4; i++) {
                    int ng = warpN * 8 + 2 * i + bsel;
                    uint32_t bd = buf + ST_B + kr * 256 + ((ng ^ (kr & 7)) << 4);
                    LDSM_X4T(bF[2*i][0], bF[2*i][1], bF[2*i+1][0], bF[2*i+1][1], bd);
                }
            }
            #pragma unroll
            for (int mt = 0; mt < 2; mt++)
                #pragma unroll
                for (int nt = 0; nt < 8; nt++) MMA(acc[mt][nt], aHi[mt], bF[nt]);
            #pragma unroll
            for (int mt = 0; mt < 2; mt++)
                #pragma unroll
                for (int nt = 0; nt < 8; nt++) MMA(acc[mt][nt], aLo[mt], bF[nt]);
        }
        __syncthreads();
        ISSUE(ch + 2);
    }

    // Epilogue: stores + fused GroupNorm partial stats
    const int b   = nBase >> 12;
    const int hwB = (nBase & 4095) + warpN * 64;
    #pragma unroll
    for (int mt = 0; mt < 2; mt++) {
        int o = oBase + warpM * 32 + mt * 16 + (lane >> 2);
        float* r0 = out + ((size_t)(b * CH + o) << 12) + hwB;
        float* r1 = r0 + ((size_t)8 << 12);
        float s0 = 0.f, q0 = 0.f, s1 = 0.f, q1 = 0.f;
        #pragma unroll
        for (int nt = 0; nt < 8; nt++) {
            int c = nt * 8 + (lane & 3) * 2;
            *(float2*)(r0 + c) = make_float2(acc[mt][nt][0], acc[mt][nt][1]);
            *(float2*)(r1 + c) = make_float2(acc[mt][nt][2], acc[mt][nt][3]);
            s0 += acc[mt][nt][0] + acc[mt][nt][1];
            q0 += acc[mt][nt][0] * acc[mt][nt][0] + acc[mt][nt][1] * acc[mt][nt][1];
            s1 += acc[mt][nt][2] + acc[mt][nt][3];
            q1 += acc[mt][nt][2] * acc[mt][nt][2] + acc[mt][nt][3] * acc[mt][nt][3];
        }
        #pragma unroll
        for (int off = 16; off > 0; off >>= 1) {
            s0 += __shfl_xor_sync(0xFFFFFFFFu, s0, off);
            q0 += __shfl_xor_sync(0xFFFFFFFFu, q0, off);
            s1 += __shfl_xor_sync(0xFFFFFFFFu, s1, off);
            q1 += __shfl_xor_sync(0xFFFFFFFFu, q1, off);
        }
        if (lane == 0) {
            int g0 = b * GROUPS + ((oBase + warpM * 32 + mt * 16) >> 3);
            atomicAdd(&g_sum[g0],     s0);
            atomicAdd(&g_sqs[g0],     q0);
            atomicAdd(&g_sum[g0 + 1], s1);
            atomicAdd(&g_sqs[g0 + 1], q1);
        }
    }
}

// ---------------------------------------------------------------------------
// 4) Normalize + affine + ReLU
// ---------------------------------------------------------------------------
__global__ void norm_relu_kernel(float* __restrict__ out,
                                 const float* __restrict__ gamma,
                                 const float* __restrict__ beta) {
    int t  = blockIdx.x * 256 + threadIdx.x;
    int i4 = t * 4;
    int b  = i4 >> 20;
    int c  = (i4 >> 12) & 255;
    int grp = b * GROUPS + (c >> 3);
    float m   = g_sum[grp] * (1.0f / GRP_ELEMS);
    float var = g_sqs[grp] * (1.0f / GRP_ELEMS) - m * m;
    float inv = rsqrtf(var + 1e-5f);
    float ga  = gamma[c] * inv;
    float be  = beta[c] - m * ga;
    float4 v = *(float4*)(out + i4);
    v.x = fmaxf(v.x * ga + be, 0.0f);
    v.y = fmaxf(v.y * ga + be, 0.0f);
    v.z = fmaxf(v.z * ga + be, 0.0f);
    v.w = fmaxf(v.w * ga + be, 0.0f);
    *(float4*)(out + i4) = v;
}

// ---------------------------------------------------------------------------
extern "C" void kernel_launch(void* const* d_in, const int* in_sizes, int n_in,
                              void* d_out, int out_size) {
    const float* x      = (const float*)d_in[0];
    const float* shp    = (const float*)d_in[1];
    const float* w_off  = (const float*)d_in[2];
    const float* w_def  = (const float*)d_in[3];
    const float* gamma  = (const float*)d_in[4];
    const float* beta   = (const float*)d_in[5];
    float* out = (float*)d_out;

    cudaFuncSetAttribute(gemm_mma_kernel,
                         cudaFuncAttributeMaxDynamicSharedMemorySize, GEMM_SMEM);

    repack_kernel<<<2304, 256>>>(w_def);
    im2col_kernel<<<dim3(8, BATCH * DGN * KKN), 256>>>(x, shp, w_off);
    gemm_mma_kernel<<<dim3(128, 2), 256, GEMM_SMEM>>>(out);
    norm_relu_kernel<<<4096, 256>>>(out, gamma, beta);
}

// round 12
// speedup vs baseline: 4.9800x; 1.4352x over previous
#include <cuda_runtime.h>
#include <cuda_fp16.h>
#include <cstdint>

// Problem constants (fixed shapes)
#define BATCH 4
#define CH    256
#define HH    64
#define WW    64
#define HWSZ  4096
#define KKN   9
#define DGN   4
#define CGN   64
#define KDIM  2304          // KKN*CH (GEMM K), k = c*9 + kk
#define NDIM  16384         // BATCH*HWSZ (GEMM N)
#define GROUPS 32
#define GRP_ELEMS 32768

// ---- scratch (device globals; allocation-free) ----
__device__ __align__(16) __half g_col[(size_t)KDIM * NDIM];   // [k][n] fp16 (75 MB)
__device__ __align__(16) __half g_wt[CH * KDIM];              // [o][k] fp16
__device__ float g_sum[BATCH * GROUPS];
__device__ float g_sqs[BATCH * GROUPS];

// ---------------------------------------------------------------------------
// PTX helpers — family-agnostic only (compute_103 target: no tcgen05/TMA)
// ---------------------------------------------------------------------------
__device__ __forceinline__ uint32_t smem_u32(const void* p) {
    uint32_t a;
    asm("{ .reg .u64 t; cvta.to.shared.u64 t, %1; cvt.u32.u64 %0, t; }" : "=r"(a) : "l"(p));
    return a;
}
__device__ __forceinline__ void cp16(uint32_t dst, const void* src) {
    asm volatile("cp.async.cg.shared.global [%0], [%1], 16;" :: "r"(dst), "l"(src) : "memory");
}
#define CP_COMMIT() asm volatile("cp.async.commit_group;" ::: "memory")
#define CP_WAIT2()  asm volatile("cp.async.wait_group 2;" ::: "memory")

#define LDSM_X4(r, addr) \
    asm volatile("ldmatrix.sync.aligned.m8n8.x4.shared.b16 {%0,%1,%2,%3}, [%4];" \
        : "=r"((r)[0]), "=r"((r)[1]), "=r"((r)[2]), "=r"((r)[3]) : "r"(addr))
#define LDSM_X4T(r0, r1, r2, r3, addr) \
    asm volatile("ldmatrix.sync.aligned.m8n8.x4.trans.shared.b16 {%0,%1,%2,%3}, [%4];" \
        : "=r"(r0), "=r"(r1), "=r"(r2), "=r"(r3) : "r"(addr))

#define MMA(d, a, b) \
    asm volatile("mma.sync.aligned.m16n8k16.row.col.f32.f16.f16.f32 " \
        "{%0,%1,%2,%3}, {%4,%5,%6,%7}, {%8,%9}, {%0,%1,%2,%3};" \
        : "+f"((d)[0]), "+f"((d)[1]), "+f"((d)[2]), "+f"((d)[3]) \
        : "r"((a)[0]), "r"((a)[1]), "r"((a)[2]), "r"((a)[3]), "r"((b)[0]), "r"((b)[1]))

// ---------------------------------------------------------------------------
// 1) Weight convert to fp16 + zero GN stat accumulators
// ---------------------------------------------------------------------------
__global__ void repack_kernel(const float* __restrict__ wd) {
    int d = blockIdx.x * 512 + threadIdx.x * 2;   // < 589824
    float2 v = *(const float2*)(wd + d);
    __half2 h = __floats2half2_rn(v.x, v.y);
    *(uint32_t*)(g_wt + d) = *(uint32_t*)&h;
    if (blockIdx.x == 0 && threadIdx.x < BATCH * GROUPS) {
        g_sum[threadIdx.x] = 0.0f;
        g_sqs[threadIdx.x] = 0.0f;
    }
}

// ---------------------------------------------------------------------------
// 2) Fused offset-projection + deformable im2col -> fp16 col [k][n]
//    Each thread handles 2 consecutive hw -> packed u32 stores.
// ---------------------------------------------------------------------------
__global__ void im2col_kernel(const float* __restrict__ x,
                              const float* __restrict__ shp,
                              const float* __restrict__ w_off) {
    int tid = threadIdx.x;
    int z  = blockIdx.y;                      // b*36 + dg*9 + kk
    int kk = z % KKN;
    int dg = (z / KKN) % DGN;
    int b  = z / (KKN * DGN);

    float w4[2][4];
    int   id[2][4];

    #pragma unroll
    for (int u = 0; u < 2; u++) {
        int hw = blockIdx.x * 512 + tid * 2 + u;
        int h  = hw >> 6;
        int w  = hw & 63;

        float s0 = shp[((b * 4 + 0) << 12) + hw];
        float s1 = shp[((b * 4 + 1) << 12) + hw];
        float s2 = shp[((b * 4 + 2) << 12) + hw];
        float s3 = shp[((b * 4 + 3) << 12) + hw];

        const float* wo = w_off + (dg * 18 + kk * 2) * 4;
        float dy = wo[0] * s0 + wo[1] * s1 + wo[2] * s2 + wo[3] * s3;
        float dx = wo[4] * s0 + wo[5] * s1 + wo[6] * s2 + wo[7] * s3;

        int ky = kk / 3, kx = kk % 3;
        float yf = (float)(h - 1 + ky) + dy;
        float xf = (float)(w - 1 + kx) + dx;
        float y0f = floorf(yf), x0f = floorf(xf);
        float wy1 = yf - y0f,  wx1 = xf - x0f;
        float wy0 = 1.0f - wy1, wx0 = 1.0f - wx1;
        int y0 = (int)y0f, x0 = (int)x0f;
        int y1 = y0 + 1,   x1 = x0 + 1;

        bool vy0 = (y0 >= 0) & (y0 < HH);
        bool vy1 = (y1 >= 0) & (y1 < HH);
        bool vx0 = (x0 >= 0) & (x0 < WW);
        bool vx1 = (x1 >= 0) & (x1 < WW);
        int y0c = min(max(y0, 0), HH - 1), y1c = min(max(y1, 0), HH - 1);
        int x0c = min(max(x0, 0), WW - 1), x1c = min(max(x1, 0), WW - 1);

        w4[u][0] = wy0 * wx0 * (float)(vy0 & vx0);
        w4[u][1] = wy0 * wx1 * (float)(vy0 & vx1);
        w4[u][2] = wy1 * wx0 * (float)(vy1 & vx0);
        w4[u][3] = wy1 * wx1 * (float)(vy1 & vx1);
        id[u][0] = y0c * WW + x0c;
        id[u][1] = y0c * WW + x1c;
        id[u][2] = y1c * WW + x0c;
        id[u][3] = y1c * WW + x1c;
    }

    const float* xb = x + ((size_t)(b * CH + dg * CGN) << 12);
    size_t nIdx = ((size_t)b << 12) + blockIdx.x * 512 + tid * 2;

    #pragma unroll 4
    for (int cg = 0; cg < CGN; cg++) {
        const float* xc = xb + ((size_t)cg << 12);
        float v0 = w4[0][0] * xc[id[0][0]] + w4[0][1] * xc[id[0][1]]
                 + w4[0][2] * xc[id[0][2]] + w4[0][3] * xc[id[0][3]];
        float v1 = w4[1][0] * xc[id[1][0]] + w4[1][1] * xc[id[1][1]]
                 + w4[1][2] * xc[id[1][2]] + w4[1][3] * xc[id[1][3]];
        int k = (dg * CGN + cg) * KKN + kk;
        __half2 hv = __floats2half2_rn(v0, v1);
        *(uint32_t*)(g_col + (size_t)k * NDIM + nIdx) = *(uint32_t*)&hv;
    }
}

// ---------------------------------------------------------------------------
// 3) fp16 HMMA GEMM: out[o][n] = sum_k wt[o][k] * col[k][n]  (f32 accum)
//    CTA 128(o) x 128(n), K-chunk 64, 3-stage cp.async, 8 warps (4x2),
//    fused GroupNorm partial-stats in epilogue.
// ---------------------------------------------------------------------------
#define KB       64
#define NCHUNK   36                 // 2304/64
#define A_STRIDE 144                // 128B data + 16B pad (conflict-free ldmatrix)
#define ST_A     0                  // 128 rows * 144B = 18432
#define ST_B     18432              // 64 rows * 256B, XOR-swizzled 16B granules
#define STAGE    34816
#define NSTAGES  3
#define GEMM_SMEM (NSTAGES * STAGE) // 104448 -> 2 CTAs/SM

#define ISSUE(ch)                                                            \
    do {                                                                     \
        if ((ch) < NCHUNK) {                                                 \
            const int k0_ = (ch) * KB;                                       \
            const uint32_t base_ = sb + ((ch) % NSTAGES) * STAGE;            \
            _Pragma("unroll")                                                \
            for (int p_ = 0; p_ < 4; p_++) {                                 \
                int a_ = tid + p_ * 256;                                     \
                int m_ = a_ >> 3, kg_ = a_ & 7;                              \
                size_t ga_ = (size_t)(oBase + m_) * KDIM + k0_ + kg_ * 8;    \
                cp16(base_ + ST_A + m_ * A_STRIDE + kg_ * 16, g_wt + ga_);   \
                int k_ = a_ >> 4, ng_ = a_ & 15;                             \
                size_t gb_ = (size_t)(k0_ + k_) * NDIM + nBase + ng_ * 8;    \
                uint32_t db_ = base_ + ST_B + k_ * 256 + ((ng_ ^ (k_ & 7)) << 4); \
                cp16(db_, g_col + gb_);                                      \
            }                                                                \
        }                                                                    \
        CP_COMMIT();                                                         \
    } while (0)

__global__ __launch_bounds__(256, 2)
void gemm_mma_kernel(float* __restrict__ out) {
    extern __shared__ __align__(128) char smem[];
    const uint32_t sb = smem_u32(smem);
    const int tid  = threadIdx.x;
    const int lane = tid & 31;
    const int wid  = tid >> 5;
    const int warpM = wid & 3;      // m offset warpM*32
    const int warpN = wid >> 2;     // n offset warpN*64
    const int nBase = blockIdx.x * 128;
    const int oBase = blockIdx.y * 128;

    float acc[2][8][4];
    #pragma unroll
    for (int mt = 0; mt < 2; mt++)
        #pragma unroll
        for (int nt = 0; nt < 8; nt++)
            #pragma unroll
            for (int q = 0; q < 4; q++) acc[mt][nt][q] = 0.0f;

    const int arow = (lane & 7) + ((lane >> 3) & 1) * 8;
    const int asel = lane >> 4;
    const int bk   = lane & 15;
    const int bsel = lane >> 4;

    ISSUE(0); ISSUE(1); ISSUE(2);

    for (int ch = 0; ch < NCHUNK; ch++) {
        CP_WAIT2();
        __syncthreads();
        const uint32_t buf = sb + (ch % NSTAGES) * STAGE;

        #pragma unroll
        for (int kq = 0; kq < 4; kq++) {
            uint32_t aF[2][4], bF[8][2];

            #pragma unroll
            for (int mt = 0; mt < 2; mt++) {
                uint32_t ad = buf + ST_A + (warpM * 32 + mt * 16 + arow) * A_STRIDE
                                  + (kq * 2 + asel) * 16;
                LDSM_X4(aF[mt], ad);
            }
            {
                int kr = kq * 16 + bk;
                #pragma unroll
                for (int i = 0; i < 4; i++) {
                    int ng = warpN * 8 + 2 * i + bsel;
                    uint32_t bd = buf + ST_B + kr * 256 + ((ng ^ (kr & 7)) << 4);
                    LDSM_X4T(bF[2*i][0], bF[2*i][1], bF[2*i+1][0], bF[2*i+1][1], bd);
                }
            }
            #pragma unroll
            for (int mt = 0; mt < 2; mt++)
                #pragma unroll
                for (int nt = 0; nt < 8; nt++) MMA(acc[mt][nt], aF[mt], bF[nt]);
        }
        __syncthreads();
        ISSUE(ch + NSTAGES);
    }

    // Epilogue: stores + fused GroupNorm partial stats
    const int b   = nBase >> 12;
    const int hwB = (nBase & 4095) + warpN * 64;
    #pragma unroll
    for (int mt = 0; mt < 2; mt++) {
        int o = oBase + warpM * 32 + mt * 16 + (lane >> 2);
        float* r0 = out + ((size_t)(b * CH + o) << 12) + hwB;
        float* r1 = r0 + ((size_t)8 << 12);
        float s0 = 0.f, q0 = 0.f, s1 = 0.f, q1 = 0.f;
        #pragma unroll
        for (int nt = 0; nt < 8; nt++) {
            int c = nt * 8 + (lane & 3) * 2;
            *(float2*)(r0 + c) = make_float2(acc[mt][nt][0], acc[mt][nt][1]);
            *(float2*)(r1 + c) = make_float2(acc[mt][nt][2], acc[mt][nt][3]);
            s0 += acc[mt][nt][0] + acc[mt][nt][1];
            q0 += acc[mt][nt][0] * acc[mt][nt][0] + acc[mt][nt][1] * acc[mt][nt][1];
            s1 += acc[mt][nt][2] + acc[mt][nt][3];
            q1 += acc[mt][nt][2] * acc[mt][nt][2] + acc[mt][nt][3] * acc[mt][nt][3];
        }
        #pragma unroll
        for (int off = 16; off > 0; off >>= 1) {
            s0 += __shfl_xor_sync(0xFFFFFFFFu, s0, off);
            q0 += __shfl_xor_sync(0xFFFFFFFFu, q0, off);
            s1 += __shfl_xor_sync(0xFFFFFFFFu, s1, off);
            q1 += __shfl_xor_sync(0xFFFFFFFFu, q1, off);
        }
        if (lane == 0) {
            int g0 = b * GROUPS + ((oBase + warpM * 32 + mt * 16) >> 3);
            atomicAdd(&g_sum[g0],     s0);
            atomicAdd(&g_sqs[g0],     q0);
            atomicAdd(&g_sum[g0 + 1], s1);
            atomicAdd(&g_sqs[g0 + 1], q1);
        }
    }
}

// ---------------------------------------------------------------------------
// 4) Normalize + affine + ReLU
// ---------------------------------------------------------------------------
__global__ void norm_relu_kernel(float* __restrict__ out,
                                 const float* __restrict__ gamma,
                                 const float* __restrict__ beta) {
    int t  = blockIdx.x * 256 + threadIdx.x;
    int i4 = t * 4;
    int b  = i4 >> 20;
    int c  = (i4 >> 12) & 255;
    int grp = b * GROUPS + (c >> 3);
    float m   = g_sum[grp] * (1.0f / GRP_ELEMS);
    float var = g_sqs[grp] * (1.0f / GRP_ELEMS) - m * m;
    float inv = rsqrtf(var + 1e-5f);
    float ga  = gamma[c] * inv;
    float be  = beta[c] - m * ga;
    float4 v = *(float4*)(out + i4);
    v.x = fmaxf(v.x * ga + be, 0.0f);
    v.y = fmaxf(v.y * ga + be, 0.0f);
    v.z = fmaxf(v.z * ga + be, 0.0f);
    v.w = fmaxf(v.w * ga + be, 0.0f);
    *(float4*)(out + i4) = v;
}

// ---------------------------------------------------------------------------
extern "C" void kernel_launch(void* const* d_in, const int* in_sizes, int n_in,
                              void* d_out, int out_size) {
    const float* x      = (const float*)d_in[0];
    const float* shp    = (const float*)d_in[1];
    const float* w_off  = (const float*)d_in[2];
    const float* w_def  = (const float*)d_in[3];
    const float* gamma  = (const float*)d_in[4];
    const float* beta   = (const float*)d_in[5];
    float* out = (float*)d_out;

    cudaFuncSetAttribute(gemm_mma_kernel,
                         cudaFuncAttributeMaxDynamicSharedMemorySize, GEMM_SMEM);

    repack_kernel<<<1152, 256>>>(w_def);
    im2col_kernel<<<dim3(8, BATCH * DGN * KKN), 256>>>(x, shp, w_off);
    gemm_mma_kernel<<<dim3(128, 2), 256, GEMM_SMEM>>>(out);
    norm_relu_kernel<<<4096, 256>>>(out, gamma, beta);
}

// round 14
// speedup vs baseline: 4.9984x; 1.0037x over previous
#include <cuda_runtime.h>
#include <cuda_fp16.h>
#include <cstdint>

// Problem constants (fixed shapes)
#define BATCH 4
#define CH    256
#define HH    64
#define WW    64
#define HWSZ  4096
#define KKN   9
#define DGN   4
#define KDIM  2304          // KKN*CH (GEMM K), ordered k' = kk*256 + c
#define NDIM  16384         // BATCH*HWSZ (GEMM N)
#define GROUPS 32
#define GRP_ELEMS 32768

// ---- scratch (device globals; allocation-free) ----
__device__ __align__(16) __half g_wt[CH * KDIM];   // [o][k'], k' = kk*256 + c
__device__ float g_sum[BATCH * GROUPS];
__device__ float g_sqs[BATCH * GROUPS];

// ---------------------------------------------------------------------------
// PTX helpers — family-agnostic only (compute_103 target: no tcgen05/TMA)
// ---------------------------------------------------------------------------
__device__ __forceinline__ uint32_t smem_u32(const void* p) {
    uint32_t a;
    asm("{ .reg .u64 t; cvta.to.shared.u64 t, %1; cvt.u32.u64 %0, t; }" : "=r"(a) : "l"(p));
    return a;
}
__device__ __forceinline__ void cp16(uint32_t dst, const void* src) {
    asm volatile("cp.async.cg.shared.global [%0], [%1], 16;" :: "r"(dst), "l"(src) : "memory");
}
#define CP_COMMIT() asm volatile("cp.async.commit_group;" ::: "memory")
#define CP_WAIT0()  asm volatile("cp.async.wait_group 0;" ::: "memory")

#define LDSM_X4(r, addr) \
    asm volatile("ldmatrix.sync.aligned.m8n8.x4.shared.b16 {%0,%1,%2,%3}, [%4];" \
        : "=r"((r)[0]), "=r"((r)[1]), "=r"((r)[2]), "=r"((r)[3]) : "r"(addr))
#define LDSM_X4T(r0, r1, r2, r3, addr) \
    asm volatile("ldmatrix.sync.aligned.m8n8.x4.trans.shared.b16 {%0,%1,%2,%3}, [%4];" \
        : "=r"(r0), "=r"(r1), "=r"(r2), "=r"(r3) : "r"(addr))

#define MMA(d, a, b) \
    asm volatile("mma.sync.aligned.m16n8k16.row.col.f32.f16.f16.f32 " \
        "{%0,%1,%2,%3}, {%4,%5,%6,%7}, {%8,%9}, {%0,%1,%2,%3};" \
        : "+f"((d)[0]), "+f"((d)[1]), "+f"((d)[2]), "+f"((d)[3]) \
        : "r"((a)[0]), "r"((a)[1]), "r"((a)[2]), "r"((a)[3]), "r"((b)[0]), "r"((b)[1]))

// ---------------------------------------------------------------------------
// 1) Weight repack to fp16, k' = kk*256 + c ordering; zero GN accumulators
//    g_wt[o*2304 + kk*256 + c] = wd[(o*256 + c)*9 + kk]
// ---------------------------------------------------------------------------
__global__ void repack_kernel(const float* __restrict__ wd) {
    int d = blockIdx.x * 256 + threadIdx.x;   // < 589824
    int o  = d / KDIM;
    int r  = d - o * KDIM;
    int kk = r >> 8;
    int c  = r & 255;
    g_wt[d] = __float2half_rn(wd[(o * CH + c) * KKN + kk]);
    if (blockIdx.x == 0 && threadIdx.x < BATCH * GROUPS) {
        g_sum[threadIdx.x] = 0.0f;
        g_sqs[threadIdx.x] = 0.0f;
    }
}

// ---------------------------------------------------------------------------
// 2) FUSED deformable-im2col + fp16 HMMA GEMM + GN partial stats.
//    CTA: M=256 (all o) x N=64 (hw). grid = 256 CTAs (b*64 + hw-tile).
//    K-chunk 64 = chunk ch -> (kk = ch>>2, dg = ch&3); 2-stage smem pipeline.
//    Producer: gather/interp B tile on the fly (col never hits DRAM).
// ---------------------------------------------------------------------------
#define NCHUNK  36
#define ST_B    32768               // A: 256 rows * 128B (XOR swizzle); B: 64 rows * 128B
#define STAGE   40960
#define GEMM_SMEM (2 * STAGE)       // 81920 -> 2 CTAs/SM

__global__ __launch_bounds__(256, 2)
void fused_gemm_kernel(float* __restrict__ out,
                       const float* __restrict__ x,
                       const float* __restrict__ shp,
                       const float* __restrict__ w_off) {
    extern __shared__ __align__(128) char smem[];
    const uint32_t sb = smem_u32(smem);
    const int tid  = threadIdx.x;
    const int lane = tid & 31;
    const int wid  = tid >> 5;
    const int b    = blockIdx.x >> 6;
    const int hwB  = (blockIdx.x & 63) * 64;

    float acc[2][8][4];
    #pragma unroll
    for (int mt = 0; mt < 2; mt++)
        #pragma unroll
        for (int nt = 0; nt < 8; nt++)
            #pragma unroll
            for (int q = 0; q < 4; q++) acc[mt][nt][q] = 0.0f;

    // ldmatrix lane geometry
    const int arow = (lane & 7) + ((lane >> 3) & 1) * 8;
    const int asel = lane >> 4;
    const int bk   = lane & 15;
    const int bsel = lane >> 4;

    // ---- producer: fill stage s with chunk ch ----
    #define PRODUCE(ch_, stg_)                                                    \
    do {                                                                          \
        const int kk_ = (ch_) >> 2, dg_ = (ch_) & 3;                              \
        /* A slab: g_wt[o][ch*64 + g*8], 2048 x 16B, XOR-swizzled rows */         \
        _Pragma("unroll")                                                         \
        for (int p_ = 0; p_ < 8; p_++) {                                          \
            int i_ = tid + p_ * 256;                                              \
            int o_ = i_ >> 3, gg_ = i_ & 7;                                       \
            cp16((stg_) + o_ * 128 + ((gg_ ^ (o_ & 7)) << 4),                     \
                 g_wt + (size_t)o_ * KDIM + (ch_) * 64 + gg_ * 8);                \
        }                                                                         \
        CP_COMMIT();                                                              \
        /* B tile: 64 k-rows x 64 n, each thread: fixed n-pair, 8 k-rows */       \
        const int np_ = tid & 31;                                                 \
        float W_[2][4]; int I_[2][4];                                             \
        _Pragma("unroll")                                                         \
        for (int u_ = 0; u_ < 2; u_++) {                                          \
            int hw_ = hwB + np_ * 2 + u_;                                         \
            int h_ = hw_ >> 6, w_ = hw_ & 63;                                     \
            float s0_ = shp[((b * 4 + 0) << 12) + hw_];                           \
            float s1_ = shp[((b * 4 + 1) << 12) + hw_];                           \
            float s2_ = shp[((b * 4 + 2) << 12) + hw_];                           \
            float s3_ = shp[((b * 4 + 3) << 12) + hw_];                           \
            const float* wo_ = w_off + (dg_ * 18 + kk_ * 2) * 4;                  \
            float dy_ = __ldg(wo_+0)*s0_ + __ldg(wo_+1)*s1_                       \
                      + __ldg(wo_+2)*s2_ + __ldg(wo_+3)*s3_;                      \
            float dx_ = __ldg(wo_+4)*s0_ + __ldg(wo_+5)*s1_                       \
                      + __ldg(wo_+6)*s2_ + __ldg(wo_+7)*s3_;                      \
            float yf_ = (float)(h_ - 1 + kk_ / 3) + dy_;                          \
            float xf_ = (float)(w_ - 1 + kk_ % 3) + dx_;                          \
            float y0f_ = floorf(yf_), x0f_ = floorf(xf_);                         \
            float wy1_ = yf_ - y0f_, wx1_ = xf_ - x0f_;                           \
            float wy0_ = 1.0f - wy1_, wx0_ = 1.0f - wx1_;                         \
            int y0_ = (int)y0f_, x0_ = (int)x0f_;                                 \
            int y1_ = y0_ + 1,   x1_ = x0_ + 1;                                   \
            bool vy0_ = (y0_ >= 0) & (y0_ < HH);                                  \
            bool vy1_ = (y1_ >= 0) & (y1_ < HH);                                  \
            bool vx0_ = (x0_ >= 0) & (x0_ < WW);                                  \
            bool vx1_ = (x1_ >= 0) & (x1_ < WW);                                  \
            int y0c_ = min(max(y0_, 0), HH-1), y1c_ = min(max(y1_, 0), HH-1);     \
            int x0c_ = min(max(x0_, 0), WW-1), x1c_ = min(max(x1_, 0), WW-1);     \
            W_[u_][0] = wy0_ * wx0_ * (float)(vy0_ & vx0_);                       \
            W_[u_][1] = wy0_ * wx1_ * (float)(vy0_ & vx1_);                       \
            W_[u_][2] = wy1_ * wx0_ * (float)(vy1_ & vx0_);                       \
            W_[u_][3] = wy1_ * wx1_ * (float)(vy1_ & vx1_);                       \
            I_[u_][0] = y0c_ * WW + x0c_;                                         \
            I_[u_][1] = y0c_ * WW + x1c_;                                         \
            I_[u_][2] = y1c_ * WW + x0c_;                                         \
            I_[u_][3] = y1c_ * WW + x1c_;                                         \
        }                                                                         \
        const float* xb_ = x + ((size_t)(b * CH + dg_ * 64) << 12);               \
        const int krB_ = tid >> 5;                                                \
        const int gn_ = np_ >> 2;                                                 \
        const uint32_t bo_ = (stg_) + ST_B + (np_ & 3) * 4;                       \
        _Pragma("unroll")                                                         \
        for (int j_ = 0; j_ < 8; j_++) {                                          \
            int kr_ = j_ * 8 + krB_;                                              \
            const float* xc_ = xb_ + ((size_t)kr_ << 12);                         \
            float v0_ = W_[0][0]*xc_[I_[0][0]] + W_[0][1]*xc_[I_[0][1]]           \
                      + W_[0][2]*xc_[I_[0][2]] + W_[0][3]*xc_[I_[0][3]];          \
            float v1_ = W_[1][0]*xc_[I_[1][0]] + W_[1][1]*xc_[I_[1][1]]           \
                      + W_[1][2]*xc_[I_[1][2]] + W_[1][3]*xc_[I_[1][3]];          \
            __half2 hv_ = __floats2half2_rn(v0_, v1_);                            \
            uint32_t a_ = bo_ + kr_ * 128 + ((gn_ ^ (kr_ & 7)) << 4);             \
            asm volatile("st.shared.b32 [%0], %1;" :: "r"(a_),                    \
                         "r"(*(uint32_t*)&hv_) : "memory");                       \
        }                                                                         \
        CP_WAIT0();                                                               \
    } while (0)

    // prologue: fill stage 0 with chunk 0
    PRODUCE(0, sb);
    __syncthreads();

    for (int ch = 0; ch < NCHUNK; ch++) {
        const uint32_t buf = sb + (ch & 1) * STAGE;

        // ---- consume chunk ch ----
        #pragma unroll
        for (int kq = 0; kq < 4; kq++) {
            uint32_t aF[2][4], bF[8][2];
            #pragma unroll
            for (int mt = 0; mt < 2; mt++) {
                int r = wid * 32 + mt * 16 + arow;
                uint32_t ad = buf + r * 128 + (((kq * 2 + asel) ^ (r & 7)) << 4);
                LDSM_X4(aF[mt], ad);
            }
            {
                int kr = kq * 16 + bk;
                #pragma unroll
                for (int i = 0; i < 4; i++) {
                    int ng = 2 * i + bsel;
                    uint32_t bd = buf + ST_B + kr * 128 + ((ng ^ (kr & 7)) << 4);
                    LDSM_X4T(bF[2*i][0], bF[2*i][1], bF[2*i+1][0], bF[2*i+1][1], bd);
                }
            }
            #pragma unroll
            for (int mt = 0; mt < 2; mt++)
                #pragma unroll
                for (int nt = 0; nt < 8; nt++) MMA(acc[mt][nt], aF[mt], bF[nt]);
        }

        // ---- produce chunk ch+1 into the other stage ----
        if (ch + 1 < NCHUNK) {
            const uint32_t nbuf = sb + ((ch + 1) & 1) * STAGE;
            PRODUCE(ch + 1, nbuf);
        }
        __syncthreads();
    }

    // ---- epilogue: stores + fused GroupNorm partial stats ----
    #pragma unroll
    for (int mt = 0; mt < 2; mt++) {
        int base = wid * 32 + mt * 16;
        int o = base + (lane >> 2);
        float* r0 = out + ((size_t)(b * CH + o) << 12) + hwB;
        float* r1 = r0 + ((size_t)8 << 12);
        float s0 = 0.f, q0 = 0.f, s1 = 0.f, q1 = 0.f;
        #pragma unroll
        for (int nt = 0; nt < 8; nt++) {
            int c = nt * 8 + (lane & 3) * 2;
            *(float2*)(r0 + c) = make_float2(acc[mt][nt][0], acc[mt][nt][1]);
            *(float2*)(r1 + c) = make_float2(acc[mt][nt][2], acc[mt][nt][3]);
            s0 += acc[mt][nt][0] + acc[mt][nt][1];
            q0 += acc[mt][nt][0] * acc[mt][nt][0] + acc[mt][nt][1] * acc[mt][nt][1];
            s1 += acc[mt][nt][2] + acc[mt][nt][3];
            q1 += acc[mt][nt][2] * acc[mt][nt][2] + acc[mt][nt][3] * acc[mt][nt][3];
        }
        #pragma unroll
        for (int off = 16; off > 0; off >>= 1) {
            s0 += __shfl_xor_sync(0xFFFFFFFFu, s0, off);
            q0 += __shfl_xor_sync(0xFFFFFFFFu, q0, off);
            s1 += __shfl_xor_sync(0xFFFFFFFFu, s1, off);
            q1 += __shfl_xor_sync(0xFFFFFFFFu, q1, off);
        }
        if (lane == 0) {
            int g0 = b * GROUPS + (base >> 3);
            atomicAdd(&g_sum[g0],     s0);
            atomicAdd(&g_sqs[g0],     q0);
            atomicAdd(&g_sum[g0 + 1], s1);
            atomicAdd(&g_sqs[g0 + 1], q1);
        }
    }
}

// ---------------------------------------------------------------------------
// 3) Normalize + affine + ReLU
// ---------------------------------------------------------------------------
__global__ void norm_relu_kernel(float* __restrict__ out,
                                 const float* __restrict__ gamma,
                                 const float* __restrict__ beta) {
    int t  = blockIdx.x * 256 + threadIdx.x;
    int i4 = t * 4;
    int b  = i4 >> 20;
    int c  = (i4 >> 12) & 255;
    int grp = b * GROUPS + (c >> 3);
    float m   = g_sum[grp] * (1.0f / GRP_ELEMS);
    float var = g_sqs[grp] * (1.0f / GRP_ELEMS) - m * m;
    float inv = rsqrtf(var + 1e-5f);
    float ga  = gamma[c] * inv;
    float be  = beta[c] - m * ga;
    float4 v = *(float4*)(out + i4);
    v.x = fmaxf(v.x * ga + be, 0.0f);
    v.y = fmaxf(v.y * ga + be, 0.0f);
    v.z = fmaxf(v.z * ga + be, 0.0f);
    v.w = fmaxf(v.w * ga + be, 0.0f);
    *(float4*)(out + i4) = v;
}

// ---------------------------------------------------------------------------
extern "C" void kernel_launch(void* const* d_in, const int* in_sizes, int n_in,
                              void* d_out, int out_size) {
    const float* x      = (const float*)d_in[0];
    const float* shp    = (const float*)d_in[1];
    const float* w_off  = (const float*)d_in[2];
    const float* w_def  = (const float*)d_in[3];
    const float* gamma  = (const float*)d_in[4];
    const float* beta   = (const float*)d_in[5];
    float* out = (float*)d_out;

    cudaFuncSetAttribute(fused_gemm_kernel,
                         cudaFuncAttributeMaxDynamicSharedMemorySize, GEMM_SMEM);

    repack_kernel<<<2304, 256>>>(w_def);
    fused_gemm_kernel<<<256, 256, GEMM_SMEM>>>(out, x, shp, w_off);
    norm_relu_kernel<<<4096, 256>>>(out, gamma, beta);
}

// round 15
// speedup vs baseline: 5.0130x; 1.0029x over previous
#include <cuda_runtime.h>
#include <cuda_fp16.h>
#include <cstdint>

// Problem constants (fixed shapes)
#define BATCH 4
#define CH    256
#define HH    64
#define WW    64
#define HWSZ  4096
#define KKN   9
#define DGN   4
#define KDIM  2304          // KKN*CH (GEMM K), ordered k' = kk*256 + c
#define NDIM  16384         // BATCH*HWSZ (GEMM N)
#define GROUPS 32
#define GRP_ELEMS 32768

// ---- scratch (device globals; allocation-free) ----
__device__ __align__(16) __half g_wt[CH * KDIM];   // [o][k'], k' = kk*256 + c
__device__ float g_sum[BATCH * GROUPS];
__device__ float g_sqs[BATCH * GROUPS];

// ---------------------------------------------------------------------------
// PTX helpers — family-agnostic only (compute_103 target: no tcgen05/TMA)
// ---------------------------------------------------------------------------
__device__ __forceinline__ uint32_t smem_u32(const void* p) {
    uint32_t a;
    asm("{ .reg .u64 t; cvta.to.shared.u64 t, %1; cvt.u32.u64 %0, t; }" : "=r"(a) : "l"(p));
    return a;
}
__device__ __forceinline__ void cp16(uint32_t dst, const void* src) {
    asm volatile("cp.async.cg.shared.global [%0], [%1], 16;" :: "r"(dst), "l"(src) : "memory");
}
#define CP_COMMIT() asm volatile("cp.async.commit_group;" ::: "memory")
#define CP_WAIT0()  asm volatile("cp.async.wait_group 0;" ::: "memory")

#define LDSM_X4(r, addr) \
    asm volatile("ldmatrix.sync.aligned.m8n8.x4.shared.b16 {%0,%1,%2,%3}, [%4];" \
        : "=r"((r)[0]), "=r"((r)[1]), "=r"((r)[2]), "=r"((r)[3]) : "r"(addr))
#define LDSM_X4T(r0, r1, r2, r3, addr) \
    asm volatile("ldmatrix.sync.aligned.m8n8.x4.trans.shared.b16 {%0,%1,%2,%3}, [%4];" \
        : "=r"(r0), "=r"(r1), "=r"(r2), "=r"(r3) : "r"(addr))

#define MMA(d, a, b) \
    asm volatile("mma.sync.aligned.m16n8k16.row.col.f32.f16.f16.f32 " \
        "{%0,%1,%2,%3}, {%4,%5,%6,%7}, {%8,%9}, {%0,%1,%2,%3};" \
        : "+f"((d)[0]), "+f"((d)[1]), "+f"((d)[2]), "+f"((d)[3]) \
        : "r"((a)[0]), "r"((a)[1]), "r"((a)[2]), "r"((a)[3]), "r"((b)[0]), "r"((b)[1]))

// ---------------------------------------------------------------------------
// 1) Weight repack to fp16, k' = kk*256 + c ordering; zero GN accumulators
//    g_wt[o*2304 + kk*256 + c] = wd[(o*256 + c)*9 + kk]
// ---------------------------------------------------------------------------
__global__ void repack_kernel(const float* __restrict__ wd) {
    int d = blockIdx.x * 256 + threadIdx.x;   // < 589824
    int o  = d / KDIM;
    int r  = d - o * KDIM;
    int kk = r >> 8;
    int c  = r & 255;
    g_wt[d] = __float2half_rn(wd[(o * CH + c) * KKN + kk]);
    if (blockIdx.x == 0 && threadIdx.x < BATCH * GROUPS) {
        g_sum[threadIdx.x] = 0.0f;
        g_sqs[threadIdx.x] = 0.0f;
    }
}

// ---------------------------------------------------------------------------
// 2) FUSED deformable-im2col + fp16 HMMA GEMM + GN partial stats.
//    CTA: M=256 (all o) x N=64 (hw). grid = 256 CTAs (b*64 + hw-tile).
//    K-chunk 64 = chunk ch -> (kk = ch>>2, dg = ch&3); 2-stage smem pipeline.
//    Producer: gather/interp B tile on the fly (col never hits DRAM).
// ---------------------------------------------------------------------------
#define NCHUNK  36
#define ST_B    32768               // A: 256 rows * 128B (XOR swizzle); B: 64 rows * 128B
#define STAGE   40960
#define GEMM_SMEM (2 * STAGE)       // 81920 -> 2 CTAs/SM

__global__ __launch_bounds__(256, 2)
void fused_gemm_kernel(float* __restrict__ out,
                       const float* __restrict__ x,
                       const float* __restrict__ shp,
                       const float* __restrict__ w_off) {
    extern __shared__ __align__(128) char smem[];
    const uint32_t sb = smem_u32(smem);
    const int tid  = threadIdx.x;
    const int lane = tid & 31;
    const int wid  = tid >> 5;
    const int b    = blockIdx.x >> 6;
    const int hwB  = (blockIdx.x & 63) * 64;

    float acc[2][8][4];
    #pragma unroll
    for (int mt = 0; mt < 2; mt++)
        #pragma unroll
        for (int nt = 0; nt < 8; nt++)
            #pragma unroll
            for (int q = 0; q < 4; q++) acc[mt][nt][q] = 0.0f;

    // ldmatrix lane geometry
    const int arow = (lane & 7) + ((lane >> 3) & 1) * 8;
    const int asel = lane >> 4;
    const int bk   = lane & 15;
    const int bsel = lane >> 4;

    // ---- producer: fill stage s with chunk ch ----
    #define PRODUCE(ch_, stg_)                                                    \
    do {                                                                          \
        const int kk_ = (ch_) >> 2, dg_ = (ch_) & 3;                              \
        /* A slab: g_wt[o][ch*64 + g*8], 2048 x 16B, XOR-swizzled rows */         \
        _Pragma("unroll")                                                         \
        for (int p_ = 0; p_ < 8; p_++) {                                          \
            int i_ = tid + p_ * 256;                                              \
            int o_ = i_ >> 3, gg_ = i_ & 7;                                       \
            cp16((stg_) + o_ * 128 + ((gg_ ^ (o_ & 7)) << 4),                     \
                 g_wt + (size_t)o_ * KDIM + (ch_) * 64 + gg_ * 8);                \
        }                                                                         \
        CP_COMMIT();                                                              \
        /* B tile: 64 k-rows x 64 n, each thread: fixed n-pair, 8 k-rows */       \
        const int np_ = tid & 31;                                                 \
        float W_[2][4]; int I_[2][4];                                             \
        _Pragma("unroll")                                                         \
        for (int u_ = 0; u_ < 2; u_++) {                                          \
            int hw_ = hwB + np_ * 2 + u_;                                         \
            int h_ = hw_ >> 6, w_ = hw_ & 63;                                     \
            float s0_ = shp[((b * 4 + 0) << 12) + hw_];                           \
            float s1_ = shp[((b * 4 + 1) << 12) + hw_];                           \
            float s2_ = shp[((b * 4 + 2) << 12) + hw_];                           \
            float s3_ = shp[((b * 4 + 3) << 12) + hw_];                           \
            const float* wo_ = w_off + (dg_ * 18 + kk_ * 2) * 4;                  \
            float dy_ = __ldg(wo_+0)*s0_ + __ldg(wo_+1)*s1_                       \
                      + __ldg(wo_+2)*s2_ + __ldg(wo_+3)*s3_;                      \
            float dx_ = __ldg(wo_+4)*s0_ + __ldg(wo_+5)*s1_                       \
                      + __ldg(wo_+6)*s2_ + __ldg(wo_+7)*s3_;                      \
            float yf_ = (float)(h_ - 1 + kk_ / 3) + dy_;                          \
            float xf_ = (float)(w_ - 1 + kk_ % 3) + dx_;                          \
            float y0f_ = floorf(yf_), x0f_ = floorf(xf_);                         \
            float wy1_ = yf_ - y0f_, wx1_ = xf_ - x0f_;                           \
            float wy0_ = 1.0f - wy1_, wx0_ = 1.0f - wx1_;                         \
            int y0_ = (int)y0f_, x0_ = (int)x0f_;                                 \
            int y1_ = y0_ + 1,   x1_ = x0_ + 1;                                   \
            bool vy0_ = (y0_ >= 0) & (y0_ < HH);                                  \
            bool vy1_ = (y1_ >= 0) & (y1_ < HH);                                  \
            bool vx0_ = (x0_ >= 0) & (x0_ < WW);                                  \
            bool vx1_ = (x1_ >= 0) & (x1_ < WW);                                  \
            int y0c_ = min(max(y0_, 0), HH-1), y1c_ = min(max(y1_, 0), HH-1);     \
            int x0c_ = min(max(x0_, 0), WW-1), x1c_ = min(max(x1_, 0), WW-1);     \
            W_[u_][0] = wy0_ * wx0_ * (float)(vy0_ & vx0_);                       \
            W_[u_][1] = wy0_ * wx1_ * (float)(vy0_ & vx1_);                       \
            W_[u_][2] = wy1_ * wx0_ * (float)(vy1_ & vx0_);                       \
            W_[u_][3] = wy1_ * wx1_ * (float)(vy1_ & vx1_);                       \
            I_[u_][0] = y0c_ * WW + x0c_;                                         \
            I_[u_][1] = y0c_ * WW + x1c_;                                         \
            I_[u_][2] = y1c_ * WW + x0c_;                                         \
            I_[u_][3] = y1c_ * WW + x1c_;                                         \
        }                                                                         \
        const float* xb_ = x + ((size_t)(b * CH + dg_ * 64) << 12);               \
        const int krB_ = tid >> 5;                                                \
        const int gn_ = np_ >> 2;                                                 \
        const uint32_t bo_ = (stg_) + ST_B + (np_ & 3) * 4;                       \
        _Pragma("unroll")                                                         \
        for (int j_ = 0; j_ < 8; j_++) {                                          \
            int kr_ = j_ * 8 + krB_;                                              \
            const float* xc_ = xb_ + ((size_t)kr_ << 12);                         \
            float v0_ = W_[0][0]*xc_[I_[0][0]] + W_[0][1]*xc_[I_[0][1]]           \
                      + W_[0][2]*xc_[I_[0][2]] + W_[0][3]*xc_[I_[0][3]];          \
            float v1_ = W_[1][0]*xc_[I_[1][0]] + W_[1][1]*xc_[I_[1][1]]           \
                      + W_[1][2]*xc_[I_[1][2]] + W_[1][3]*xc_[I_[1][3]];          \
            __half2 hv_ = __floats2half2_rn(v0_, v1_);                            \
            uint32_t a_ = bo_ + kr_ * 128 + ((gn_ ^ (kr_ & 7)) << 4);             \
            asm volatile("st.shared.b32 [%0], %1;" :: "r"(a_),                    \
                         "r"(*(uint32_t*)&hv_) : "memory");                       \
        }                                                                         \
        CP_WAIT0();                                                               \
    } while (0)

    // prologue: fill stage 0 with chunk 0
    PRODUCE(0, sb);
    __syncthreads();

    for (int ch = 0; ch < NCHUNK; ch++) {
        const uint32_t buf = sb + (ch & 1) * STAGE;

        // ---- consume chunk ch ----
        #pragma unroll
        for (int kq = 0; kq < 4; kq++) {
            uint32_t aF[2][4], bF[8][2];
            #pragma unroll
            for (int mt = 0; mt < 2; mt++) {
                int r = wid * 32 + mt * 16 + arow;
                uint32_t ad = buf + r * 128 + (((kq * 2 + asel) ^ (r & 7)) << 4);
                LDSM_X4(aF[mt], ad);
            }
            {
                int kr = kq * 16 + bk;
                #pragma unroll
                for (int i = 0; i < 4; i++) {
                    int ng = 2 * i + bsel;
                    uint32_t bd = buf + ST_B + kr * 128 + ((ng ^ (kr & 7)) << 4);
                    LDSM_X4T(bF[2*i][0], bF[2*i][1], bF[2*i+1][0], bF[2*i+1][1], bd);
                }
            }
            #pragma unroll
            for (int mt = 0; mt < 2; mt++)
                #pragma unroll
                for (int nt = 0; nt < 8; nt++) MMA(acc[mt][nt], aF[mt], bF[nt]);
        }

        // ---- produce chunk ch+1 into the other stage ----
        if (ch + 1 < NCHUNK) {
            const uint32_t nbuf = sb + ((ch + 1) & 1) * STAGE;
            PRODUCE(ch + 1, nbuf);
        }
        __syncthreads();
    }

    // ---- epilogue: stores + fused GroupNorm partial stats ----
    #pragma unroll
    for (int mt = 0; mt < 2; mt++) {
        int base = wid * 32 + mt * 16;
        int o = base + (lane >> 2);
        float* r0 = out + ((size_t)(b * CH + o) << 12) + hwB;
        float* r1 = r0 + ((size_t)8 << 12);
        float s0 = 0.f, q0 = 0.f, s1 = 0.f, q1 = 0.f;
        #pragma unroll
        for (int nt = 0; nt < 8; nt++) {
            int c = nt * 8 + (lane & 3) * 2;
            *(float2*)(r0 + c) = make_float2(acc[mt][nt][0], acc[mt][nt][1]);
            *(float2*)(r1 + c) = make_float2(acc[mt][nt][2], acc[mt][nt][3]);
            s0 += acc[mt][nt][0] + acc[mt][nt][1];
            q0 += acc[mt][nt][0] * acc[mt][nt][0] + acc[mt][nt][1] * acc[mt][nt][1];
            s1 += acc[mt][nt][2] + acc[mt][nt][3];
            q1 += acc[mt][nt][2] * acc[mt][nt][2] + acc[mt][nt][3] * acc[mt][nt][3];
        }
        #pragma unroll
        for (int off = 16; off > 0; off >>= 1) {
            s0 += __shfl_xor_sync(0xFFFFFFFFu, s0, off);
            q0 += __shfl_xor_sync(0xFFFFFFFFu, q0, off);
            s1 += __shfl_xor_sync(0xFFFFFFFFu, s1, off);
            q1 += __shfl_xor_sync(0xFFFFFFFFu, q1, off);
        }
        if (lane == 0) {
            int g0 = b * GROUPS + (base >> 3);
            atomicAdd(&g_sum[g0],     s0);
            atomicAdd(&g_sqs[g0],     q0);
            atomicAdd(&g_sum[g0 + 1], s1);
            atomicAdd(&g_sqs[g0 + 1], q1);
        }
    }
}

// ---------------------------------------------------------------------------
// 3) Normalize + affine + ReLU
// ---------------------------------------------------------------------------
__global__ void norm_relu_kernel(float* __restrict__ out,
                                 const float* __restrict__ gamma,
                                 const float* __restrict__ beta) {
    int t  = blockIdx.x * 256 + threadIdx.x;
    int i4 = t * 4;
    int b  = i4 >> 20;
    int c  = (i4 >> 12) & 255;
    int grp = b * GROUPS + (c >> 3);
    float m   = g_sum[grp] * (1.0f / GRP_ELEMS);
    float var = g_sqs[grp] * (1.0f / GRP_ELEMS) - m * m;
    float inv = rsqrtf(var + 1e-5f);
    float ga  = gamma[c] * inv;
    float be  = beta[c] - m * ga;
    float4 v = *(float4*)(out + i4);
    v.x = fmaxf(v.x * ga + be, 0.0f);
    v.y = fmaxf(v.y * ga + be, 0.0f);
    v.z = fmaxf(v.z * ga + be, 0.0f);
    v.w = fmaxf(v.w * ga + be, 0.0f);
    *(float4*)(out + i4) = v;
}

// ---------------------------------------------------------------------------
extern "C" void kernel_launch(void* const* d_in, const int* in_sizes, int n_in,
                              void* d_out, int out_size) {
    const float* x      = (const float*)d_in[0];
    const float* shp    = (const float*)d_in[1];
    const float* w_off  = (const float*)d_in[2];
    const float* w_def  = (const float*)d_in[3];
    const float* gamma  = (const float*)d_in[4];
    const float* beta   = (const float*)d_in[5];
    float* out = (float*)d_out;

    cudaFuncSetAttribute(fused_gemm_kernel,
                         cudaFuncAttributeMaxDynamicSharedMemorySize, GEMM_SMEM);

    repack_kernel<<<2304, 256>>>(w_def);
    fused_gemm_kernel<<<256, 256, GEMM_SMEM>>>(out, x, shp, w_off);
    norm_relu_kernel<<<4096, 256>>>(out, gamma, beta);
}